// round 7
// baseline (speedup 1.0000x reference)
#include <cuda_runtime.h>
#include <cuda_bf16.h>
#include <cstdint>

// Problem constants
#define BATCH 64
#define OUTF  8192
#define INF   8192
#define RANK  16
#define GROUP 16
#define KC    64              // K chunk per stage
#define NCHUNK (INF / KC)     // 128
#define OUT_TILE 64
#define NBLOCKS (OUTF / OUT_TILE)  // 128

__constant__ float c_lut[16] = {
    0.0f, 0.5f, 1.0f, 1.5f, 2.0f, 3.0f, 4.0f, 6.0f,
    -0.0f, -0.5f, -1.0f, -1.5f, -2.0f, -3.0f, -4.0f, -6.0f
};

// scratch for lora intermediate t = x @ A^T  (64 x 16)
__device__ float g_t[BATCH * RANK];

__device__ __forceinline__ unsigned tf32_rna(float x) {
    unsigned r;
    asm("cvt.rna.tf32.f32 %0, %1;" : "=r"(r) : "f"(x));
    return r;
}
__device__ __forceinline__ float tf32f(float x) {
    return __uint_as_float(tf32_rna(x));
}

__device__ __forceinline__ void mma_tf32_16x8x8(
    float& c0, float& c1, float& c2, float& c3,
    unsigned a0, unsigned a1, unsigned a2, unsigned a3,
    unsigned b0, unsigned b1)
{
    asm volatile(
        "mma.sync.aligned.m16n8k8.row.col.f32.tf32.tf32.f32 "
        "{%0,%1,%2,%3}, {%4,%5,%6,%7}, {%8,%9}, {%0,%1,%2,%3};"
        : "+f"(c0), "+f"(c1), "+f"(c2), "+f"(c3)
        : "r"(a0), "r"(a1), "r"(a2), "r"(a3), "r"(b0), "r"(b1));
}

// ---------------------------------------------------------------------------
// Kernel 0: t[b][r] = sum_i x[b][i] * A[r][i]   (fp32 exact)
// ---------------------------------------------------------------------------
__global__ __launch_bounds__(256) void lora_t_kernel(
    const float* __restrict__ x, const float* __restrict__ A)
{
    const int b = blockIdx.x;
    const int tid = threadIdx.x;
    const int r = tid & 15;
    const int part = tid >> 4;         // 0..15, each owns 512 contiguous elems

    const float* xr = x + (size_t)b * INF + part * 512;
    const float* ar = A + (size_t)r * INF + part * 512;

    float s = 0.0f;
    #pragma unroll 4
    for (int j = 0; j < 512; j += 4) {
        float4 xv = *reinterpret_cast<const float4*>(xr + j);
        float4 av = *reinterpret_cast<const float4*>(ar + j);
        s += xv.x * av.x + xv.y * av.y + xv.z * av.z + xv.w * av.w;
    }

    __shared__ float red[256];
    red[tid] = s;
    __syncthreads();
    if (tid < 16) {
        float t = 0.0f;
        #pragma unroll
        for (int p = 0; p < 16; p++) t += red[p * 16 + tid];
        g_t[b * RANK + tid] = t;
    }
}

// ---------------------------------------------------------------------------
// Main kernel: dequant nvfp4 (stored as int32-per-byte!) -> tf32 mma -> lora
//  grid = 128 CTAs (one 64-row OUT tile each), 256 threads (8 warps)
//  warp tile: m16 (out) x n32 (batch), 4 n-subtiles of 8
// ---------------------------------------------------------------------------
__global__ __launch_bounds__(256) void qlora_main_kernel(
    const float* __restrict__ x,
    const int* __restrict__ pw,        // one packed BYTE per int32 element
    const float* __restrict__ sc,
    const float* __restrict__ lB,
    float* __restrict__ out)
{
    __shared__ float  W_s[OUT_TILE][KC + 4];   // [o][k], pad 68
    __shared__ float  x_s[KC][BATCH + 4];      // [k][b], pad 68
    __shared__ float2 lut2[256];
    __shared__ float  lb_s[OUT_TILE * RANK];   // 1024
    __shared__ float  t_s[BATCH * RANK];       // 1024

    const int tid  = threadIdx.x;
    const int lane = tid & 31;
    const int warp = tid >> 5;
    const int o0   = blockIdx.x * OUT_TILE;

    // byte -> (low nibble val, high nibble val); low nibble = even index
    if (tid < 256) {
        lut2[tid] = make_float2(c_lut[tid & 15], c_lut[tid >> 4]);
    }

    // ---- staging thread roles ----
    // W: thread -> (row = tid>>2, group = tid&3): 1 scale + 8 byte-codes = 16 weights
    const int wrow = tid >> 2;
    const int wg   = tid & 3;
    const int* pw_row = pw + (size_t)(o0 + wrow) * (INF / 2) + wg * 8;
    const float* sc_row = sc + (size_t)(o0 + wrow) * (INF / GROUP) + wg;
    // x: thread -> (b = tid>>2, 4 float4's at cols (tid&3)*4 + 16p)
    const int xb  = tid >> 2;
    const int xk0 = (tid & 3) * 4;
    const float* x_row = x + (size_t)xb * INF;

    // warp tiling
    const int m0  = (warp & 3) * 16;       // out sub-tile
    const int nb  = (warp >> 2) * 32;      // batch half
    const int gid = lane >> 2;
    const int tig = lane & 3;

    float acc[4][4];
    #pragma unroll
    for (int j = 0; j < 4; j++)
        #pragma unroll
        for (int e = 0; e < 4; e++) acc[j][e] = 0.0f;

    // ---- prefetch chunk 0 ----
    uint4 pa = *reinterpret_cast<const uint4*>(pw_row);
    uint4 pb = *reinterpret_cast<const uint4*>(pw_row + 4);
    float scr = sc_row[0];
    float4 xr[4];
    #pragma unroll
    for (int p = 0; p < 4; p++)
        xr[p] = *reinterpret_cast<const float4*>(x_row + xk0 + 16 * p);

    for (int c = 0; c < NCHUNK; c++) {
        __syncthreads();   // prev mma phase done reading smem (also fences lut2 at c=0)

        // ---- decode W (16 values) -> W_s, tf32-rounded ----
        {
            unsigned codes[8] = { pa.x, pa.y, pa.z, pa.w, pb.x, pb.y, pb.z, pb.w };
            float wv[16];
            #pragma unroll
            for (int j = 0; j < 8; j++) {
                float2 d = lut2[codes[j] & 0xFF];
                wv[2 * j]     = tf32f(d.x * scr);
                wv[2 * j + 1] = tf32f(d.y * scr);
            }
            #pragma unroll
            for (int q = 0; q < 4; q++) {
                *reinterpret_cast<float4*>(&W_s[wrow][wg * 16 + q * 4]) =
                    make_float4(wv[q * 4], wv[q * 4 + 1], wv[q * 4 + 2], wv[q * 4 + 3]);
            }
        }
        // ---- x transpose -> x_s, tf32-rounded ----
        #pragma unroll
        for (int p = 0; p < 4; p++) {
            const int kk = xk0 + 16 * p;
            x_s[kk + 0][xb] = tf32f(xr[p].x);
            x_s[kk + 1][xb] = tf32f(xr[p].y);
            x_s[kk + 2][xb] = tf32f(xr[p].z);
            x_s[kk + 3][xb] = tf32f(xr[p].w);
        }

        __syncthreads();   // tiles ready

        // ---- prefetch next chunk (global latency hides behind mma phase) ----
        if (c + 1 < NCHUNK) {
            const int kn = (c + 1) * KC;
            const int* pn = pw_row + (c + 1) * (KC / 2);
            pa = *reinterpret_cast<const uint4*>(pn);
            pb = *reinterpret_cast<const uint4*>(pn + 4);
            scr = sc_row[(c + 1) * (KC / GROUP)];
            #pragma unroll
            for (int p = 0; p < 4; p++)
                xr[p] = *reinterpret_cast<const float4*>(x_row + kn + xk0 + 16 * p);
        }

        // ---- mma phase: 8 k8-steps ----
        #pragma unroll
        for (int s = 0; s < 8; s++) {
            const int kl = s * 8;
            unsigned a0 = __float_as_uint(W_s[m0 + gid][kl + tig]);
            unsigned a1 = __float_as_uint(W_s[m0 + gid + 8][kl + tig]);
            unsigned a2 = __float_as_uint(W_s[m0 + gid][kl + tig + 4]);
            unsigned a3 = __float_as_uint(W_s[m0 + gid + 8][kl + tig + 4]);
            #pragma unroll
            for (int j = 0; j < 4; j++) {
                unsigned b0 = __float_as_uint(x_s[kl + tig][nb + 8 * j + gid]);
                unsigned b1 = __float_as_uint(x_s[kl + tig + 4][nb + 8 * j + gid]);
                mma_tf32_16x8x8(acc[j][0], acc[j][1], acc[j][2], acc[j][3],
                                a0, a1, a2, a3, b0, b1);
            }
        }
    }

    // ---- epilogue: += lora, store ----
    __syncthreads();
    for (int i = tid; i < OUT_TILE * RANK; i += 256) {
        lb_s[i] = lB[(size_t)o0 * RANK + i];   // lora_B rows o0..o0+63 are contiguous
        t_s[i]  = g_t[i];                      // 64*16 == 64*16
    }
    __syncthreads();

    float lbr0[RANK], lbr1[RANK];
    #pragma unroll
    for (int r = 0; r < RANK; r++) {
        lbr0[r] = lb_s[(m0 + gid) * RANK + r];
        lbr1[r] = lb_s[(m0 + gid + 8) * RANK + r];
    }

    #pragma unroll
    for (int j = 0; j < 4; j++) {
        const int bc0 = nb + 8 * j + 2 * tig;
        const int bc1 = bc0 + 1;
        float d00 = 0.f, d01 = 0.f, d10 = 0.f, d11 = 0.f;
        #pragma unroll
        for (int r = 0; r < RANK; r++) {
            const float t0 = t_s[bc0 * RANK + r];
            const float t1 = t_s[bc1 * RANK + r];
            d00 += t0 * lbr0[r];
            d01 += t1 * lbr0[r];
            d10 += t0 * lbr1[r];
            d11 += t1 * lbr1[r];
        }
        const int og0 = o0 + m0 + gid;
        out[(size_t)bc0 * OUTF + og0]     = acc[j][0] + d00;
        out[(size_t)bc1 * OUTF + og0]     = acc[j][1] + d01;
        out[(size_t)bc0 * OUTF + og0 + 8] = acc[j][2] + d10;
        out[(size_t)bc1 * OUTF + og0 + 8] = acc[j][3] + d11;
    }
}

// ---------------------------------------------------------------------------
// launch
// inputs (metadata order): x f32(64,8192), packed_weight int32(8192,4096)
//   (uint8 widened to int32 by the harness: one byte-code per element),
//   weight_block_scales f32(8192,512), lora_A f32(16,8192), lora_B f32(8192,16)
// output: f32 (64,8192)
// ---------------------------------------------------------------------------
extern "C" void kernel_launch(void* const* d_in, const int* in_sizes, int n_in,
                              void* d_out, int out_size)
{
    const float* x   = (const float*)d_in[0];
    const int*   pw  = (const int*)d_in[1];
    const float* sc  = (const float*)d_in[2];
    const float* lA  = (const float*)d_in[3];
    const float* lB  = (const float*)d_in[4];
    float*       out = (float*)d_out;

    lora_t_kernel<<<BATCH, 256>>>(x, lA);
    qlora_main_kernel<<<NBLOCKS, 256>>>(x, pw, sc, lB, out);
}

// round 8
// speedup vs baseline: 1.2929x; 1.2929x over previous
#include <cuda_runtime.h>
#include <cuda_bf16.h>
#include <cstdint>

// Problem constants
#define BATCH 64
#define OUTF  8192
#define INF   8192
#define RANK  16
#define GROUP 16
#define KC    64              // K chunk per stage
#define NCHUNK (INF / KC)     // 128
#define OUT_TILE 64
#define NBLOCKS (OUTF / OUT_TILE)  // 128

#define XS_STRIDE 72          // x_s row stride (k-major): 72 mod 32 == 8 -> conflict-free B reads
#define WS_STRIDE 68          // W_s row stride (o-major): conflict-free A reads, 272B = 16B-aligned

// scratch: lora intermediate t = x @ A^T (64x16), and tf32-rounded transposed x
__device__ float g_t[BATCH * RANK];
__device__ __align__(16) float g_xt[INF * BATCH];   // [k][b], 2 MB

__device__ __forceinline__ unsigned tf32_rna(float x) {
    unsigned r;
    asm("cvt.rna.tf32.f32 %0, %1;" : "=r"(r) : "f"(x));
    return r;
}
__device__ __forceinline__ float tf32f(float x) {
    return __uint_as_float(tf32_rna(x));
}

// nvfp4 (e2m1) nibble -> fp32, times scale. n in [0,16).
// mags: 0,0.5,1,1.5,2,3,4,6 ; bit3 = sign
__device__ __forceinline__ float dec4(unsigned n, float scr) {
    unsigned m = n & 7u;
    unsigned man = (m & ((m >> 1) | (m >> 2))) & 1u;    // mantissa bit: odd and >1
    unsigned bits = ((126u + (m >> 1)) << 23) | (man << 22);
    if (m == 0u) bits = 0u;
    bits |= (n & 8u) << 28;                              // sign
    return __uint_as_float(bits) * scr;
}

__device__ __forceinline__ void mma_tf32_16x8x8(
    float& c0, float& c1, float& c2, float& c3,
    unsigned a0, unsigned a1, unsigned a2, unsigned a3,
    unsigned b0, unsigned b1)
{
    asm volatile(
        "mma.sync.aligned.m16n8k8.row.col.f32.tf32.tf32.f32 "
        "{%0,%1,%2,%3}, {%4,%5,%6,%7}, {%8,%9}, {%0,%1,%2,%3};"
        : "+f"(c0), "+f"(c1), "+f"(c2), "+f"(c3)
        : "r"(a0), "r"(a1), "r"(a2), "r"(a3), "r"(b0), "r"(b1));
}

// ---------------------------------------------------------------------------
// Prep kernel (fused):
//  blocks [0,64):    t[b][r] = sum_i x[b][i] * A[r][i]        (fp32 exact)
//  blocks [64,192):  x_t[k][b] = tf32(x[b][k])  for one 64-k slab
// ---------------------------------------------------------------------------
__global__ __launch_bounds__(256) void prep_kernel(
    const float* __restrict__ x, const float* __restrict__ A)
{
    __shared__ float ts[64][65];   // also covers the 256-float reduction buffer
    const int tid = threadIdx.x;

    if (blockIdx.x < BATCH) {
        // ---- lora t ----
        const int b = blockIdx.x;
        const int r = tid & 15;
        const int part = tid >> 4;

        const float* xr = x + (size_t)b * INF + part * 512;
        const float* ar = A + (size_t)r * INF + part * 512;

        float s = 0.0f;
        #pragma unroll 4
        for (int j = 0; j < 512; j += 4) {
            float4 xv = *reinterpret_cast<const float4*>(xr + j);
            float4 av = *reinterpret_cast<const float4*>(ar + j);
            s += xv.x * av.x + xv.y * av.y + xv.z * av.z + xv.w * av.w;
        }
        float* red = &ts[0][0];
        red[tid] = s;
        __syncthreads();
        if (tid < 16) {
            float t = 0.0f;
            #pragma unroll
            for (int p = 0; p < 16; p++) t += red[p * 16 + tid];
            g_t[b * RANK + tid] = t;
        }
    } else {
        // ---- x transpose slab: k in [k0, k0+64) ----
        const int k0 = (blockIdx.x - BATCH) * 64;
        const int b = tid >> 2;        // 0..63
        const int q = tid & 3;         // 0..3
        const float4* x4 = reinterpret_cast<const float4*>(x);

        #pragma unroll
        for (int p = 0; p < 4; p++) {
            float4 v = x4[(size_t)b * (INF / 4) + (k0 >> 2) + q * 4 + p];
            const int kk = q * 16 + p * 4;
            ts[kk + 0][b] = v.x;
            ts[kk + 1][b] = v.y;
            ts[kk + 2][b] = v.z;
            ts[kk + 3][b] = v.w;
        }
        __syncthreads();

        float4* out4 = reinterpret_cast<float4*>(g_xt) + (size_t)(blockIdx.x - BATCH) * 1024;
        #pragma unroll
        for (int p = 0; p < 4; p++) {
            const int f = tid + 256 * p;
            const int k = f >> 4;
            const int c = (f & 15) * 4;
            out4[f] = make_float4(tf32f(ts[k][c + 0]), tf32f(ts[k][c + 1]),
                                  tf32f(ts[k][c + 2]), tf32f(ts[k][c + 3]));
        }
    }
}

// ---------------------------------------------------------------------------
// Main kernel: dequant nvfp4 (int32-per-byte) -> tf32 mma -> lora epilogue
//  grid = 128 CTAs (one 64-row OUT tile), 256 threads (8 warps)
//  warp tile: m16 (out) x n32 (batch)
// ---------------------------------------------------------------------------
__global__ __launch_bounds__(256) void qlora_main_kernel(
    const int* __restrict__ pw,        // one packed BYTE per int32 element
    const float* __restrict__ sc,
    const float* __restrict__ lB,
    float* __restrict__ out)
{
    __shared__ float W_s[OUT_TILE * WS_STRIDE];   // [o][k]
    __shared__ float x_s[KC * XS_STRIDE];         // [k][b]
    __shared__ float lb_s[OUT_TILE * RANK];
    __shared__ float t_s[BATCH * RANK];

    const int tid  = threadIdx.x;
    const int lane = tid & 31;
    const int warp = tid >> 5;
    const int o0   = blockIdx.x * OUT_TILE;

    // ---- staging roles ----
    // W: wg = (tid>>3)&3 (k-group of 16), wrow = (tid&7)|((tid>>5)<<3)
    //    -> per STS.128 phase, banks 4*wrow covers {0,4,...,28}: conflict-free
    const int wg   = (tid >> 3) & 3;
    const int wrow = (tid & 7) | ((tid >> 5) << 3);
    const int* pw_row = pw + (size_t)(o0 + wrow) * (INF / 2) + wg * 8;
    const float* sc_row = sc + (size_t)(o0 + wrow) * (INF / GROUP) + wg;

    // warp tiling
    const int m0  = (warp & 3) * 16;       // out sub-tile
    const int nb  = (warp >> 2) * 32;      // batch half
    const int gid = lane >> 2;
    const int tig = lane & 3;

    float acc[4][4];
    #pragma unroll
    for (int j = 0; j < 4; j++)
        #pragma unroll
        for (int e = 0; e < 4; e++) acc[j][e] = 0.0f;

    // ---- prefetch chunk 0 ----
    uint4 pa = *reinterpret_cast<const uint4*>(pw_row);
    uint4 pb = *reinterpret_cast<const uint4*>(pw_row + 4);
    float scr = sc_row[0];
    float4 xr[4];
    {
        const float4* src = reinterpret_cast<const float4*>(g_xt);
        #pragma unroll
        for (int p = 0; p < 4; p++) xr[p] = src[tid + 256 * p];
    }

    for (int c = 0; c < NCHUNK; c++) {
        __syncthreads();   // prev mma phase done reading smem

        // ---- decode W (16 values, arithmetic e2m1) -> W_s ----
        {
            unsigned codes[8] = { pa.x, pa.y, pa.z, pa.w, pb.x, pb.y, pb.z, pb.w };
            float wv[16];
            #pragma unroll
            for (int j = 0; j < 8; j++) {
                const unsigned cb = codes[j] & 0xFFu;
                wv[2 * j]     = tf32f(dec4(cb & 15u, scr));
                wv[2 * j + 1] = tf32f(dec4(cb >> 4, scr));
            }
            float* wdst = &W_s[wrow * WS_STRIDE + wg * 16];
            #pragma unroll
            for (int q = 0; q < 4; q++) {
                *reinterpret_cast<float4*>(wdst + q * 4) =
                    make_float4(wv[q * 4], wv[q * 4 + 1], wv[q * 4 + 2], wv[q * 4 + 3]);
            }
        }
        // ---- x tile: vectorized copy from pre-transposed g_xt into stride-72 smem ----
        #pragma unroll
        for (int p = 0; p < 4; p++) {
            const int f = tid + 256 * p;           // float4 index within chunk
            const int k = f >> 4;
            const int cc = (f & 15) * 4;
            *reinterpret_cast<float4*>(&x_s[k * XS_STRIDE + cc]) = xr[p];
        }

        __syncthreads();   // tiles ready

        // ---- prefetch next chunk ----
        if (c + 1 < NCHUNK) {
            const int* pn = pw_row + (c + 1) * (KC / 2);
            pa = *reinterpret_cast<const uint4*>(pn);
            pb = *reinterpret_cast<const uint4*>(pn + 4);
            scr = sc_row[(c + 1) * (KC / GROUP)];
            const float4* src = reinterpret_cast<const float4*>(g_xt) + (size_t)(c + 1) * 1024;
            #pragma unroll
            for (int p = 0; p < 4; p++) xr[p] = src[tid + 256 * p];
        }

        // ---- mma phase: 8 k8-steps ----
        #pragma unroll
        for (int s = 0; s < 8; s++) {
            const int kl = s * 8;
            // A reads: bank = (4*gid + tig) mod 32 -> conflict-free
            unsigned a0 = __float_as_uint(W_s[(m0 + gid) * WS_STRIDE + kl + tig]);
            unsigned a1 = __float_as_uint(W_s[(m0 + gid + 8) * WS_STRIDE + kl + tig]);
            unsigned a2 = __float_as_uint(W_s[(m0 + gid) * WS_STRIDE + kl + tig + 4]);
            unsigned a3 = __float_as_uint(W_s[(m0 + gid + 8) * WS_STRIDE + kl + tig + 4]);
            #pragma unroll
            for (int j = 0; j < 4; j++) {
                // B reads: bank = (8*tig + gid) mod 32 -> conflict-free
                unsigned b0 = __float_as_uint(x_s[(kl + tig) * XS_STRIDE + nb + 8 * j + gid]);
                unsigned b1 = __float_as_uint(x_s[(kl + tig + 4) * XS_STRIDE + nb + 8 * j + gid]);
                mma_tf32_16x8x8(acc[j][0], acc[j][1], acc[j][2], acc[j][3],
                                a0, a1, a2, a3, b0, b1);
            }
        }
    }

    // ---- epilogue: += lora, store ----
    __syncthreads();
    for (int i = tid; i < OUT_TILE * RANK; i += 256) {
        lb_s[i] = lB[(size_t)o0 * RANK + i];   // lora_B rows o0..o0+63 contiguous
        t_s[i]  = g_t[i];
    }
    __syncthreads();

    float lbr0[RANK], lbr1[RANK];
    #pragma unroll
    for (int r = 0; r < RANK; r++) {
        lbr0[r] = lb_s[(m0 + gid) * RANK + r];
        lbr1[r] = lb_s[(m0 + gid + 8) * RANK + r];
    }

    #pragma unroll
    for (int j = 0; j < 4; j++) {
        const int bc0 = nb + 8 * j + 2 * tig;
        const int bc1 = bc0 + 1;
        float d00 = 0.f, d01 = 0.f, d10 = 0.f, d11 = 0.f;
        #pragma unroll
        for (int r = 0; r < RANK; r++) {
            const float t0 = t_s[bc0 * RANK + r];
            const float t1 = t_s[bc1 * RANK + r];
            d00 += t0 * lbr0[r];
            d01 += t1 * lbr0[r];
            d10 += t0 * lbr1[r];
            d11 += t1 * lbr1[r];
        }
        const int og0 = o0 + m0 + gid;
        out[(size_t)bc0 * OUTF + og0]     = acc[j][0] + d00;
        out[(size_t)bc1 * OUTF + og0]     = acc[j][1] + d01;
        out[(size_t)bc0 * OUTF + og0 + 8] = acc[j][2] + d10;
        out[(size_t)bc1 * OUTF + og0 + 8] = acc[j][3] + d11;
    }
}

// ---------------------------------------------------------------------------
// launch
// inputs: x f32(64,8192), packed_weight int32(8192,4096) [byte per element],
//   weight_block_scales f32(8192,512), lora_A f32(16,8192), lora_B f32(8192,16)
// output: f32 (64,8192)
// ---------------------------------------------------------------------------
extern "C" void kernel_launch(void* const* d_in, const int* in_sizes, int n_in,
                              void* d_out, int out_size)
{
    const float* x   = (const float*)d_in[0];
    const int*   pw  = (const int*)d_in[1];
    const float* sc  = (const float*)d_in[2];
    const float* lA  = (const float*)d_in[3];
    const float* lB  = (const float*)d_in[4];
    float*       out = (float*)d_out;

    prep_kernel<<<BATCH + NCHUNK, 256>>>(x, lA);
    qlora_main_kernel<<<NBLOCKS, 256>>>(pw, sc, lB, out);
}

// round 10
// speedup vs baseline: 1.8173x; 1.4056x over previous
#include <cuda_runtime.h>
#include <cuda_bf16.h>
#include <cstdint>

// Problem constants
#define BATCH 64
#define OUTF  8192
#define INF   8192
#define RANK  16
#define GROUP 16
#define KC    64              // K chunk per stage
#define NCHUNK (INF / KC)     // 128
#define NCHUNK_HALF (NCHUNK / 2)   // 64 per split-K CTA
#define OUT_TILE 64
#define NOTILES (OUTF / OUT_TILE)  // 128
#define NBLOCKS (2 * NOTILES)      // 256: x2 split-K

#define XS_STRIDE 72          // x_s row stride (k-major): conflict-free B reads
#define WS_STRIDE 68          // W_s row stride (o-major): conflict-free A reads

// scratch: lora t (64x16), tf32-rounded transposed x (2MB), split-K partials (4MB)
__device__ float g_t[BATCH * RANK];
__device__ __align__(16) float g_xt[INF * BATCH];
__device__ __align__(16) float g_p[2 * BATCH * OUTF];

__device__ __forceinline__ unsigned tf32_rna(float x) {
    unsigned r;
    asm("cvt.rna.tf32.f32 %0, %1;" : "=r"(r) : "f"(x));
    return r;
}
__device__ __forceinline__ float tf32f(float x) {
    return __uint_as_float(tf32_rna(x));
}

// nvfp4 (e2m1) nibble -> fp32, times scale. n in [0,16).
__device__ __forceinline__ float dec4(unsigned n, float scr) {
    unsigned m = n & 7u;
    unsigned man = (m & ((m >> 1) | (m >> 2))) & 1u;
    unsigned bits = ((126u + (m >> 1)) << 23) | (man << 22);
    if (m == 0u) bits = 0u;
    bits |= (n & 8u) << 28;
    return __uint_as_float(bits) * scr;
}

__device__ __forceinline__ void mma_tf32_16x8x8(
    float& c0, float& c1, float& c2, float& c3,
    unsigned a0, unsigned a1, unsigned a2, unsigned a3,
    unsigned b0, unsigned b1)
{
    asm volatile(
        "mma.sync.aligned.m16n8k8.row.col.f32.tf32.tf32.f32 "
        "{%0,%1,%2,%3}, {%4,%5,%6,%7}, {%8,%9}, {%0,%1,%2,%3};"
        : "+f"(c0), "+f"(c1), "+f"(c2), "+f"(c3)
        : "r"(a0), "r"(a1), "r"(a2), "r"(a3), "r"(b0), "r"(b1));
}

// ---------------------------------------------------------------------------
// Prep kernel (fused):
//  blocks [0,64):    t[b][r] = sum_i x[b][i] * A[r][i]        (fp32 exact)
//  blocks [64,192):  x_t[k][b] = tf32(x[b][k])  for one 64-k slab
// ---------------------------------------------------------------------------
__global__ __launch_bounds__(256) void prep_kernel(
    const float* __restrict__ x, const float* __restrict__ A)
{
    __shared__ float ts[64][65];
    const int tid = threadIdx.x;

    if (blockIdx.x < BATCH) {
        const int b = blockIdx.x;
        const int r = tid & 15;
        const int part = tid >> 4;

        const float* xr = x + (size_t)b * INF + part * 512;
        const float* ar = A + (size_t)r * INF + part * 512;

        float s = 0.0f;
        #pragma unroll 4
        for (int j = 0; j < 512; j += 4) {
            float4 xv = *reinterpret_cast<const float4*>(xr + j);
            float4 av = *reinterpret_cast<const float4*>(ar + j);
            s += xv.x * av.x + xv.y * av.y + xv.z * av.z + xv.w * av.w;
        }
        float* red = &ts[0][0];
        red[tid] = s;
        __syncthreads();
        if (tid < 16) {
            float t = 0.0f;
            #pragma unroll
            for (int p = 0; p < 16; p++) t += red[p * 16 + tid];
            g_t[b * RANK + tid] = t;
        }
    } else {
        const int k0 = (blockIdx.x - BATCH) * 64;
        const int b = tid >> 2;
        const int q = tid & 3;
        const float4* x4 = reinterpret_cast<const float4*>(x);

        #pragma unroll
        for (int p = 0; p < 4; p++) {
            float4 v = x4[(size_t)b * (INF / 4) + (k0 >> 2) + q * 4 + p];
            const int kk = q * 16 + p * 4;
            ts[kk + 0][b] = v.x;
            ts[kk + 1][b] = v.y;
            ts[kk + 2][b] = v.z;
            ts[kk + 3][b] = v.w;
        }
        __syncthreads();

        float4* out4 = reinterpret_cast<float4*>(g_xt) + (size_t)(blockIdx.x - BATCH) * 1024;
        #pragma unroll
        for (int p = 0; p < 4; p++) {
            const int f = tid + 256 * p;
            const int k = f >> 4;
            const int c = (f & 15) * 4;
            out4[f] = make_float4(tf32f(ts[k][c + 0]), tf32f(ts[k][c + 1]),
                                  tf32f(ts[k][c + 2]), tf32f(ts[k][c + 3]));
        }
    }
}

// ---------------------------------------------------------------------------
// Main kernel: split-K=2 dequant+tf32 mma.
//  grid = 256: blockIdx = otile | (khalf << 7). 256 threads (8 warps).
//  khalf CTA accumulates k in [khalf*4096, +4096) and writes partial g_p[khalf];
//  khalf==0 CTA also folds in the lora term.
// ---------------------------------------------------------------------------
__global__ __launch_bounds__(256, 2) void qlora_main_kernel(
    const int* __restrict__ pw,        // one packed BYTE per int32 element
    const float* __restrict__ sc,
    const float* __restrict__ lB)
{
    __shared__ float W_s[OUT_TILE * WS_STRIDE];
    __shared__ float x_s[KC * XS_STRIDE];
    __shared__ float lb_s[OUT_TILE * RANK];
    __shared__ float t_s[BATCH * RANK];

    const int tid   = threadIdx.x;
    const int lane  = tid & 31;
    const int warp  = tid >> 5;
    const int otile = blockIdx.x & (NOTILES - 1);
    const int khalf = blockIdx.x >> 7;
    const int o0    = otile * OUT_TILE;

    // ---- staging roles (conflict-free STS.128 phases) ----
    const int wg   = (tid >> 3) & 3;
    const int wrow = (tid & 7) | ((tid >> 5) << 3);
    const int* pw_row = pw + (size_t)(o0 + wrow) * (INF / 2)
                           + (size_t)khalf * (INF / 4) + wg * 8;
    const float* sc_row = sc + (size_t)(o0 + wrow) * (INF / GROUP)
                             + khalf * (INF / (2 * GROUP)) + wg;
    const float4* xt4 = reinterpret_cast<const float4*>(g_xt)
                      + (size_t)khalf * NCHUNK_HALF * 1024;

    // warp tiling
    const int m0  = (warp & 3) * 16;
    const int nb  = (warp >> 2) * 32;
    const int gid = lane >> 2;
    const int tig = lane & 3;

    float acc[4][4];
    #pragma unroll
    for (int j = 0; j < 4; j++)
        #pragma unroll
        for (int e = 0; e < 4; e++) acc[j][e] = 0.0f;

    // ---- prefetch chunk 0 ----
    uint4 pa = *reinterpret_cast<const uint4*>(pw_row);
    uint4 pb = *reinterpret_cast<const uint4*>(pw_row + 4);
    float scr = sc_row[0];
    float4 xr[4];
    #pragma unroll
    for (int p = 0; p < 4; p++) xr[p] = xt4[tid + 256 * p];

    for (int c = 0; c < NCHUNK_HALF; c++) {
        __syncthreads();   // prev mma phase done reading smem

        // ---- decode W (16 values, arithmetic e2m1) -> W_s ----
        {
            unsigned codes[8] = { pa.x, pa.y, pa.z, pa.w, pb.x, pb.y, pb.z, pb.w };
            float wv[16];
            #pragma unroll
            for (int j = 0; j < 8; j++) {
                const unsigned cb = codes[j] & 0xFFu;
                wv[2 * j]     = tf32f(dec4(cb & 15u, scr));
                wv[2 * j + 1] = tf32f(dec4(cb >> 4, scr));
            }
            float* wdst = &W_s[wrow * WS_STRIDE + wg * 16];
            #pragma unroll
            for (int q = 0; q < 4; q++) {
                *reinterpret_cast<float4*>(wdst + q * 4) =
                    make_float4(wv[q * 4], wv[q * 4 + 1], wv[q * 4 + 2], wv[q * 4 + 3]);
            }
        }
        // ---- x tile: vectorized copy into stride-72 smem ----
        #pragma unroll
        for (int p = 0; p < 4; p++) {
            const int f = tid + 256 * p;
            const int k = f >> 4;
            const int cc = (f & 15) * 4;
            *reinterpret_cast<float4*>(&x_s[k * XS_STRIDE + cc]) = xr[p];
        }

        __syncthreads();   // tiles ready

        // ---- prefetch next chunk ----
        if (c + 1 < NCHUNK_HALF) {
            const int* pn = pw_row + (c + 1) * (KC / 2);
            pa = *reinterpret_cast<const uint4*>(pn);
            pb = *reinterpret_cast<const uint4*>(pn + 4);
            scr = sc_row[(c + 1) * (KC / GROUP)];
            const float4* src = xt4 + (size_t)(c + 1) * 1024;
            #pragma unroll
            for (int p = 0; p < 4; p++) xr[p] = src[tid + 256 * p];
        }

        // ---- mma phase: 8 k8-steps ----
        #pragma unroll
        for (int s = 0; s < 8; s++) {
            const int kl = s * 8;
            unsigned a0 = __float_as_uint(W_s[(m0 + gid) * WS_STRIDE + kl + tig]);
            unsigned a1 = __float_as_uint(W_s[(m0 + gid + 8) * WS_STRIDE + kl + tig]);
            unsigned a2 = __float_as_uint(W_s[(m0 + gid) * WS_STRIDE + kl + tig + 4]);
            unsigned a3 = __float_as_uint(W_s[(m0 + gid + 8) * WS_STRIDE + kl + tig + 4]);
            #pragma unroll
            for (int j = 0; j < 4; j++) {
                unsigned b0 = __float_as_uint(x_s[(kl + tig) * XS_STRIDE + nb + 8 * j + gid]);
                unsigned b1 = __float_as_uint(x_s[(kl + tig + 4) * XS_STRIDE + nb + 8 * j + gid]);
                mma_tf32_16x8x8(acc[j][0], acc[j][1], acc[j][2], acc[j][3],
                                a0, a1, a2, a3, b0, b1);
            }
        }
    }

    // ---- epilogue ----
    float* pout = g_p + (size_t)khalf * BATCH * OUTF;

    if (khalf == 0) {
        // fold lora into the khalf-0 partial
        __syncthreads();
        for (int i = tid; i < OUT_TILE * RANK; i += 256) {
            lb_s[i] = lB[(size_t)o0 * RANK + i];
            t_s[i]  = g_t[i];
        }
        __syncthreads();

        float lbr0[RANK], lbr1[RANK];
        #pragma unroll
        for (int r = 0; r < RANK; r++) {
            lbr0[r] = lb_s[(m0 + gid) * RANK + r];
            lbr1[r] = lb_s[(m0 + gid + 8) * RANK + r];
        }

        #pragma unroll
        for (int j = 0; j < 4; j++) {
            const int bc0 = nb + 8 * j + 2 * tig;
            const int bc1 = bc0 + 1;
            float d00 = 0.f, d01 = 0.f, d10 = 0.f, d11 = 0.f;
            #pragma unroll
            for (int r = 0; r < RANK; r++) {
                const float t0 = t_s[bc0 * RANK + r];
                const float t1 = t_s[bc1 * RANK + r];
                d00 += t0 * lbr0[r];
                d01 += t1 * lbr0[r];
                d10 += t0 * lbr1[r];
                d11 += t1 * lbr1[r];
            }
            const int og0 = o0 + m0 + gid;
            pout[(size_t)bc0 * OUTF + og0]     = acc[j][0] + d00;
            pout[(size_t)bc1 * OUTF + og0]     = acc[j][1] + d01;
            pout[(size_t)bc0 * OUTF + og0 + 8] = acc[j][2] + d10;
            pout[(size_t)bc1 * OUTF + og0 + 8] = acc[j][3] + d11;
        }
    } else {
        #pragma unroll
        for (int j = 0; j < 4; j++) {
            const int bc0 = nb + 8 * j + 2 * tig;
            const int bc1 = bc0 + 1;
            const int og0 = o0 + m0 + gid;
            pout[(size_t)bc0 * OUTF + og0]     = acc[j][0];
            pout[(size_t)bc1 * OUTF + og0]     = acc[j][1];
            pout[(size_t)bc0 * OUTF + og0 + 8] = acc[j][2];
            pout[(size_t)bc1 * OUTF + og0 + 8] = acc[j][3];
        }
    }
}

// ---------------------------------------------------------------------------
// Reduce kernel: out = p0 + p1 (elementwise, float4)
// ---------------------------------------------------------------------------
__global__ __launch_bounds__(256) void reduce_kernel(float* __restrict__ out)
{
    const int i = blockIdx.x * 256 + threadIdx.x;      // float4 index
    const float4* p0 = reinterpret_cast<const float4*>(g_p);
    const float4* p1 = p0 + (BATCH * OUTF) / 4;
    float4 a = p0[i];
    float4 b = p1[i];
    reinterpret_cast<float4*>(out)[i] =
        make_float4(a.x + b.x, a.y + b.y, a.z + b.z, a.w + b.w);
}

// ---------------------------------------------------------------------------
// launch
// inputs: x f32(64,8192), packed_weight int32(8192,4096) [byte per element],
//   weight_block_scales f32(8192,512), lora_A f32(16,8192), lora_B f32(8192,16)
// output: f32 (64,8192)
// ---------------------------------------------------------------------------
extern "C" void kernel_launch(void* const* d_in, const int* in_sizes, int n_in,
                              void* d_out, int out_size)
{
    const float* x   = (const float*)d_in[0];
    const int*   pw  = (const int*)d_in[1];
    const float* sc  = (const float*)d_in[2];
    const float* lA  = (const float*)d_in[3];
    const float* lB  = (const float*)d_in[4];
    float*       out = (float*)d_out;

    prep_kernel<<<BATCH + NCHUNK, 256>>>(x, lA);
    qlora_main_kernel<<<NBLOCKS, 256>>>(pw, sc, lB);
    reduce_kernel<<<(BATCH * OUTF / 4) / 256, 256>>>(out);
}